// round 14
// baseline (speedup 1.0000x reference)
#include <cuda_runtime.h>

#define HH 128
#define WW 128
#define CC 64
#define NPIX (HH*WW)
#define GSTR 129
#define ASTR 132   // attn A stride: quad-stride 33 ≡ 1 mod 8 -> conflict-free LDS.128
#define QSTR 68    // rowgram Qt/Kt stride

typedef unsigned long long u64;

__device__ __forceinline__ u64 fma2(u64 a, u64 b, u64 c) {
    u64 d;
    asm("fma.rn.f32x2 %0, %1, %2, %3;" : "=l"(d) : "l"(a), "l"(b), "l"(c));
    return d;
}
__device__ __forceinline__ u64 pack2(float x, float y) {
    u64 d;
    asm("mov.b64 %0, {%1, %2};" : "=l"(d) : "f"(x), "f"(y));
    return d;
}
__device__ __forceinline__ float2 unpack2(u64 v) {
    float2 r;
    asm("mov.b64 {%0, %1}, %2;" : "=f"(r.x), "=f"(r.y) : "l"(v));
    return r;
}

// scratch (allocation-free: __device__ globals)
__device__ float g_q[HH*WW*CC];   // [h][w][c]  (c contiguous)
__device__ float g_k[HH*WW*CC];   // [h][w][c]
__device__ float g_S[HH*WW*WW];   // [r][w][k]  (after prefix: PS over r)
__device__ float g_tmp[CC*HH*WW]; // [c][h][k]  hsum of v; after prefix: prefix over h

// ---------------------------------------------------------------------------
// Fused QKV: grid (128, 3) = (h, dest); 512 threads; 1 image row per block.
// ---------------------------------------------------------------------------
__global__ __launch_bounds__(512) void qkv_kernel(const float* __restrict__ x,
                                                  const float* __restrict__ Wq,
                                                  const float* __restrict__ bq,
                                                  const float* __restrict__ Wk,
                                                  const float* __restrict__ bk,
                                                  const float* __restrict__ Wv,
                                                  const float* __restrict__ bv)
{
    extern __shared__ float dsm[];
    float* Ws   = dsm;          // [ch][c] 64x64
    float* bs   = dsm + 4096;
    float* vbuf = dsm + 4160;   // [ch][w] 64x128 (dest==2 only)

    int h = blockIdx.x;
    int dest = blockIdx.y;
    const float* Wm   = (dest == 0) ? Wq : (dest == 1) ? Wk : Wv;
    const float* bias = (dest == 0) ? bq : (dest == 1) ? bk : bv;
    int tid = threadIdx.x;
    for (int i = tid; i < 4096; i += 512) Ws[i] = Wm[i];
    if (tid < 64) bs[tid] = bias[tid];
    __syncthreads();

    int slot = tid & 127;            // w
    int quarter = tid >> 7;          // 16-channel group
    int ch0 = quarter * 16;
    int n = h * 128 + slot;

    u64 acc[16];
    #pragma unroll
    for (int i = 0; i < 16; i++) acc[i] = 0ull;

    #pragma unroll 4
    for (int c = 0; c < 64; c += 2) {
        float xa = x[c * NPIX + n];
        float xb = x[(c + 1) * NPIX + n];
        u64 xp = pack2(xa, xb);
        #pragma unroll
        for (int i = 0; i < 16; i++) {
            u64 wp = *(const u64*)&Ws[(ch0 + i) * 64 + c];
            acc[i] = fma2(xp, wp, acc[i]);
        }
    }

    if (dest < 2) {
        float* out = (dest == 0) ? g_q : g_k;
        float vals[16];
        #pragma unroll
        for (int i = 0; i < 16; i++) {
            float2 u = unpack2(acc[i]);
            vals[i] = u.x + u.y + bs[ch0 + i];
        }
        float* dst = out + h * (WW*CC) + slot * CC + ch0;
        #pragma unroll
        for (int i = 0; i < 4; i++)
            *(float4*)(dst + i*4) = make_float4(vals[i*4], vals[i*4+1],
                                                vals[i*4+2], vals[i*4+3]);
    } else {
        #pragma unroll
        for (int i = 0; i < 16; i++) {
            float2 u = unpack2(acc[i]);
            vbuf[(ch0 + i) * 128 + slot] = u.x + u.y + bs[ch0 + i];
        }
        __syncthreads();
        int klo = (slot - 3 < 0) ? 0 : slot - 3;
        int khi = (slot + 3 > 127) ? 127 : slot + 3;
        #pragma unroll
        for (int i = 0; i < 16; i++) {
            const float* vr = vbuf + (ch0 + i) * 128;
            float s = 0.f;
            for (int kk = klo; kk <= khi; kk++) s += vr[kk];
            g_tmp[(ch0 + i) * NPIX + h * 128 + slot] = s;
        }
    }
}

// ---------------------------------------------------------------------------
// Per-row Gram G_r = Q_r K_r^T over c (c-contiguous, f32x2-packed),
// then diagonal 7-sum -> S_r. 128 blocks x 512 threads.
// ---------------------------------------------------------------------------
__global__ __launch_bounds__(512) void rowgram_kernel()
{
    extern __shared__ float sm[];
    float* Qt = sm;                    // [w][c] stride QSTR
    float* Kt = sm + 128*QSTR;         // [w][c] stride QSTR
    float* G  = sm + 2*128*QSTR;       // [a][b] stride GSTR

    int r = blockIdx.x;
    int tid = threadIdx.x;
    const float4* qrow = (const float4*)(g_q + r * 8192);
    const float4* krow = (const float4*)(g_k + r * 8192);
    for (int i = tid; i < 2048; i += 512) {
        int w = i >> 4, c4 = (i & 15) * 4;
        *(float4*)&Qt[w*QSTR + c4] = qrow[i];
        *(float4*)&Kt[w*QSTR + c4] = krow[i];
    }
    __syncthreads();

    int lane = tid & 31, warp = tid >> 5;    // 16 warps
    int b0 = warp * 8;
    u64 acc[4][8];
    #pragma unroll
    for (int m = 0; m < 4; m++)
        #pragma unroll
        for (int j = 0; j < 8; j++) acc[m][j] = 0ull;

    #pragma unroll 2
    for (int cc = 0; cc < 64; cc += 4) {
        ulonglong2 q4[4];
        #pragma unroll
        for (int m = 0; m < 4; m++)
            q4[m] = *(const ulonglong2*)&Qt[(lane + 32*m)*QSTR + cc];
        #pragma unroll
        for (int j = 0; j < 8; j++) {
            ulonglong2 k4 = *(const ulonglong2*)&Kt[(b0 + j)*QSTR + cc];
            #pragma unroll
            for (int m = 0; m < 4; m++) {
                acc[m][j] = fma2(q4[m].x, k4.x, acc[m][j]);
                acc[m][j] = fma2(q4[m].y, k4.y, acc[m][j]);
            }
        }
    }
    #pragma unroll
    for (int m = 0; m < 4; m++)
        #pragma unroll
        for (int j = 0; j < 8; j++) {
            float2 u = unpack2(acc[m][j]);
            G[(lane + 32*m)*GSTR + b0 + j] = u.x + u.y;
        }
    __syncthreads();

    float* Sout = g_S + r * 16384;
    for (int idx = tid; idx < 16384; idx += 512) {
        int w = idx >> 7, k = idx & 127;
        float s = 0.f;
        #pragma unroll
        for (int j = 0; j < 7; j++) {
            int a = w - 3 + j, b = k - 3 + j;
            if (a >= 0 && a < 128 && b >= 0 && b < 128)
                s += G[a*GSTR + b];
        }
        Sout[idx] = s;
    }
}

// ---------------------------------------------------------------------------
// In-place prefix sums: g_S over r (16384 scalar chains), g_tmp over h (8192).
// 192 blocks x 128 threads (spread across all SMs); MLP = 16 per batch.
// ---------------------------------------------------------------------------
__global__ __launch_bounds__(128) void prefix_kernel()
{
    int t = blockIdx.x * 128 + threadIdx.x;
    float vals[16];
    if (t < 16384) {
        float s = 0.f;
        float* p = g_S + t;
        #pragma unroll
        for (int rb = 0; rb < 128; rb += 16) {
            #pragma unroll
            for (int i = 0; i < 16; i++) vals[i] = p[(rb + i) * 16384];
            #pragma unroll
            for (int i = 0; i < 16; i++) { s += vals[i]; p[(rb + i) * 16384] = s; }
        }
    } else {
        int u = t - 16384;
        int c = u >> 7, k = u & 127;
        float s = 0.f;
        float* p = g_tmp + c * NPIX + k;
        #pragma unroll
        for (int hb = 0; hb < 128; hb += 16) {
            #pragma unroll
            for (int i = 0; i < 16; i++) vals[i] = p[(hb + i) * 128];
            #pragma unroll
            for (int i = 0; i < 16; i++) { s += vals[i]; p[(hb + i) * 128] = s; }
        }
    }
}

// ---------------------------------------------------------------------------
// Per (h, w-quarter): A = PS diff; softmax_k; Vs = Ptmp diff; out = attn@Vs^T.
// 512 blocks x 512 threads, smem ~49.7KB -> 3+ blocks/SM, good wave packing.
// Thread GEMM tile: 2c x 2w with w pair {wg, wg+16} (conflict-free LDS.128).
// ---------------------------------------------------------------------------
__global__ __launch_bounds__(512) void attn_out_kernel(float* __restrict__ out)
{
    extern __shared__ float sm[];
    float* A  = sm;                 // [32 local w][k], stride ASTR
    float* Vs = sm + 32*ASTR;       // [c=64][k=128]

    int h       = blockIdx.x >> 2;
    int quarter = blockIdx.x & 3;
    int tid = threadIdx.x;
    int lane = tid & 31, warp = tid >> 5;    // 16 warps

    int r0 = (h - 3 < 0) ? 0 : h - 3;
    int r1 = (h + 3 > 127) ? 127 : h + 3;
    const float4* P1 = (const float4*)(g_S + r1 * 16384 + quarter * 4096);
    const float4* P0 = (r0 > 0) ? (const float4*)(g_S + (r0 - 1) * 16384 + quarter * 4096) : nullptr;
    for (int i4 = tid; i4 < 1024; i4 += 512) {
        float4 s = P1[i4];
        if (P0) {
            float4 b = P0[i4];
            s.x -= b.x; s.y -= b.y; s.z -= b.z; s.w -= b.w;
        }
        int wl = i4 >> 5, k = (i4 & 31) * 4;
        *(float4*)(A + wl*ASTR + k) = s;
    }

    int top = (h + 3 > 127) ? 127 : h + 3;
    int bot = h - 4;
    const float4* T4 = (const float4*)g_tmp;
    float4* Vs4 = (float4*)Vs;
    for (int i4 = tid; i4 < 2048; i4 += 512) {
        int c = i4 >> 5, kq = i4 & 31;
        float4 s = T4[c*4096 + top*32 + kq];
        if (bot >= 0) {
            float4 b = T4[c*4096 + bot*32 + kq];
            s.x -= b.x; s.y -= b.y; s.z -= b.z; s.w -= b.w;
        }
        Vs4[c*32 + kq] = s;
    }
    __syncthreads();

    // softmax over k: one warp per local-w row (16 warps, 32 rows)
    for (int w = warp; w < 32; w += 16) {
        float v[4];
        #pragma unroll
        for (int m = 0; m < 4; m++) v[m] = A[w*ASTR + lane + 32*m];
        float mx = fmaxf(fmaxf(v[0], v[1]), fmaxf(v[2], v[3]));
        #pragma unroll
        for (int off = 16; off > 0; off >>= 1)
            mx = fmaxf(mx, __shfl_xor_sync(0xffffffffu, mx, off));
        float e[4], s = 0.f;
        #pragma unroll
        for (int m = 0; m < 4; m++) { e[m] = __expf(v[m] - mx); s += e[m]; }
        #pragma unroll
        for (int off = 16; off > 0; off >>= 1)
            s += __shfl_xor_sync(0xffffffffu, s, off);
        float inv = 1.f / s;
        #pragma unroll
        for (int m = 0; m < 4; m++) A[w*ASTR + lane + 32*m] = e[m] * inv;
    }
    __syncthreads();

    // out[c, h, quarter*32 + w] = sum_k A[w][k] * Vs[c][k]
    // thread tile: w in {wg, wg+16} (wg = lane&15), c in {c0, c0+1}
    int wg = lane & 15;
    int c0 = warp * 4 + (lane >> 4) * 2;
    u64 acc[2][2];
    #pragma unroll
    for (int i = 0; i < 2; i++)
        #pragma unroll
        for (int m = 0; m < 2; m++) acc[i][m] = 0ull;

    #pragma unroll 4
    for (int k = 0; k < 128; k += 4) {
        ulonglong2 a0 = *(const ulonglong2*)&A[wg*ASTR + k];
        ulonglong2 a1 = *(const ulonglong2*)&A[(wg + 16)*ASTR + k];
        ulonglong2 v0 = *(const ulonglong2*)&Vs[c0*128 + k];
        ulonglong2 v1 = *(const ulonglong2*)&Vs[(c0 + 1)*128 + k];
        acc[0][0] = fma2(v0.x, a0.x, acc[0][0]);
        acc[0][0] = fma2(v0.y, a0.y, acc[0][0]);
        acc[0][1] = fma2(v0.x, a1.x, acc[0][1]);
        acc[0][1] = fma2(v0.y, a1.y, acc[0][1]);
        acc[1][0] = fma2(v1.x, a0.x, acc[1][0]);
        acc[1][0] = fma2(v1.y, a0.y, acc[1][0]);
        acc[1][1] = fma2(v1.x, a1.x, acc[1][1]);
        acc[1][1] = fma2(v1.y, a1.y, acc[1][1]);
    }
    int wbase = h*128 + quarter*32;
    #pragma unroll
    for (int i = 0; i < 2; i++)
        #pragma unroll
        for (int m = 0; m < 2; m++) {
            float2 u = unpack2(acc[i][m]);
            out[(c0 + i)*NPIX + wbase + wg + 16*m] = u.x + u.y;
        }
}

// ---------------------------------------------------------------------------
extern "C" void kernel_launch(void* const* d_in, const int* in_sizes, int n_in,
                              void* d_out, int out_size)
{
    const float* x  = (const float*)d_in[0];
    const float* Wq = (const float*)d_in[1];
    const float* bq = (const float*)d_in[2];
    const float* Wk = (const float*)d_in[3];
    const float* bk = (const float*)d_in[4];
    const float* Wv = (const float*)d_in[5];
    const float* bv = (const float*)d_in[6];
    float* out = (float*)d_out;

    const int smem1 = (4096 + 64 + 64*128) * 4;          //  49664 B
    const int smem2 = (2*128*QSTR + 128*GSTR) * 4;       // 135680 B
    const int smem4 = (32*ASTR + 64*128) * 4;            //  49664 B
    cudaFuncSetAttribute(qkv_kernel,      cudaFuncAttributeMaxDynamicSharedMemorySize, smem1);
    cudaFuncSetAttribute(rowgram_kernel,  cudaFuncAttributeMaxDynamicSharedMemorySize, smem2);
    cudaFuncSetAttribute(attn_out_kernel, cudaFuncAttributeMaxDynamicSharedMemorySize, smem4);

    dim3 qkv_grid(128, 3);
    qkv_kernel<<<qkv_grid, 512, smem1>>>(x, Wq, bq, Wk, bk, Wv, bv);
    rowgram_kernel<<<128, 512, smem2>>>();
    prefix_kernel<<<192, 128>>>();
    attn_out_kernel<<<512, 512, smem4>>>(out);
}

// round 15
// speedup vs baseline: 1.6698x; 1.6698x over previous
#include <cuda_runtime.h>

#define HH 128
#define WW 128
#define CC 64
#define NPIX (HH*WW)
#define GSTR 129
#define ASTR 132   // attn A stride: ≡4 mod 32 -> conflict-free lane-strided LDS.128
#define QSTR 68    // Qt/Kt stride: quad-stride 17 -> conflict-free LDS.128

typedef unsigned long long u64;

__device__ __forceinline__ u64 fma2(u64 a, u64 b, u64 c) {
    u64 d;
    asm("fma.rn.f32x2 %0, %1, %2, %3;" : "=l"(d) : "l"(a), "l"(b), "l"(c));
    return d;
}
__device__ __forceinline__ u64 pack2(float x, float y) {
    u64 d;
    asm("mov.b64 %0, {%1, %2};" : "=l"(d) : "f"(x), "f"(y));
    return d;
}
__device__ __forceinline__ float2 unpack2(u64 v) {
    float2 r;
    asm("mov.b64 {%0, %1}, %2;" : "=f"(r.x), "=f"(r.y) : "l"(v));
    return r;
}

// scratch (allocation-free: __device__ globals)
__device__ float g_S[HH*WW*WW];   // [r][w][k]  (after prefix: PS over r)
__device__ float g_tmp[CC*HH*WW]; // [c][h][k]  hsum of v; after prefix: prefix over h

// ---------------------------------------------------------------------------
// Fused Q/K projection + row Gram + diagonal 7-sum. One block per image row.
// smem (floats): Qt[128*68] | Kt[128*68] | G[128*129]
// During phases 1-2, G's space doubles as: Xs[64*128] Wsq[4096] Wsk[4096]
// bsq[64] bsk[64] (8192+8192+128 = 16512 = |G| exactly).
// ---------------------------------------------------------------------------
__global__ __launch_bounds__(512) void qkgram_kernel(const float* __restrict__ x,
                                                     const float* __restrict__ Wq,
                                                     const float* __restrict__ bq,
                                                     const float* __restrict__ Wk,
                                                     const float* __restrict__ bk)
{
    extern __shared__ float sm[];
    float* Qt = sm;                 // [w][c] stride QSTR
    float* Kt = sm + 8704;          // [w][c] stride QSTR
    float* G  = sm + 17408;         // [a][b] stride GSTR (phase 3+)
    float* Xs  = G;                 // [c][w] 64x128     (phases 1-2)
    float* Wsq = G + 8192;          // [ch][c] 64x64
    float* Wsk = G + 12288;         // [ch][c] 64x64
    float* bsq = G + 16384;
    float* bsk = G + 16448;

    int h = blockIdx.x;
    int tid = threadIdx.x;

    // ---- phase 1: stage x row + both weight matrices ----
    const float* xrow = x + h * 128;
    for (int i = tid; i < 8192; i += 512) {
        int c = i >> 7, w = i & 127;
        Xs[i] = xrow[c * NPIX + w];
    }
    for (int i = tid; i < 4096; i += 512) { Wsq[i] = Wq[i]; Wsk[i] = Wk[i]; }
    if (tid < 64) { bsq[tid] = bq[tid]; bsk[tid] = bk[tid]; }
    __syncthreads();

    int slot = tid & 127;            // w
    int quarter = tid >> 7;          // 16-channel group
    int ch0 = quarter * 16;

    // ---- phase 2: q,k projections for this row (c-reduction f32x2-packed) ----
    {
        u64 accq[16], acck[16];
        #pragma unroll
        for (int i = 0; i < 16; i++) { accq[i] = 0ull; acck[i] = 0ull; }

        #pragma unroll 4
        for (int c = 0; c < 64; c += 2) {
            u64 xp = pack2(Xs[c*128 + slot], Xs[(c+1)*128 + slot]);
            #pragma unroll
            for (int i = 0; i < 16; i++) {
                accq[i] = fma2(xp, *(const u64*)&Wsq[(ch0 + i)*64 + c], accq[i]);
                acck[i] = fma2(xp, *(const u64*)&Wsk[(ch0 + i)*64 + c], acck[i]);
            }
        }
        #pragma unroll
        for (int i = 0; i < 16; i++) {
            float2 uq = unpack2(accq[i]);
            Qt[slot*QSTR + ch0 + i] = uq.x + uq.y + bsq[ch0 + i];
            float2 uk = unpack2(acck[i]);
            Kt[slot*QSTR + ch0 + i] = uk.x + uk.y + bsk[ch0 + i];
        }
    }
    __syncthreads();

    // ---- phase 3: Gram G[a][b] = sum_c Qt[a][c]*Kt[b][c] (overwrites Xs/Ws) ----
    int lane = tid & 31, warp = tid >> 5;    // 16 warps
    int b0 = warp * 8;
    {
        u64 acc[4][8];
        #pragma unroll
        for (int m = 0; m < 4; m++)
            #pragma unroll
            for (int j = 0; j < 8; j++) acc[m][j] = 0ull;

        #pragma unroll 2
        for (int cc = 0; cc < 64; cc += 4) {
            ulonglong2 q4[4];
            #pragma unroll
            for (int m = 0; m < 4; m++)
                q4[m] = *(const ulonglong2*)&Qt[(lane + 32*m)*QSTR + cc];
            #pragma unroll
            for (int j = 0; j < 8; j++) {
                ulonglong2 k4 = *(const ulonglong2*)&Kt[(b0 + j)*QSTR + cc];
                #pragma unroll
                for (int m = 0; m < 4; m++) {
                    acc[m][j] = fma2(q4[m].x, k4.x, acc[m][j]);
                    acc[m][j] = fma2(q4[m].y, k4.y, acc[m][j]);
                }
            }
        }
        #pragma unroll
        for (int m = 0; m < 4; m++)
            #pragma unroll
            for (int j = 0; j < 8; j++) {
                float2 u = unpack2(acc[m][j]);
                G[(lane + 32*m)*GSTR + b0 + j] = u.x + u.y;
            }
    }
    __syncthreads();

    // ---- phase 4: S_r[w,k] = sum_{j=0..6} G[w-3+j, k-3+j] ----
    float* Sout = g_S + h * 16384;
    for (int idx = tid; idx < 16384; idx += 512) {
        int w = idx >> 7, k = idx & 127;
        float s = 0.f;
        #pragma unroll
        for (int j = 0; j < 7; j++) {
            int a = w - 3 + j, b = k - 3 + j;
            if (a >= 0 && a < 128 && b >= 0 && b < 128)
                s += G[a*GSTR + b];
        }
        Sout[idx] = s;
    }
}

// ---------------------------------------------------------------------------
// V projection + horizontal 7-tap sum -> g_tmp[c][h][w]. One block per row.
// Dynamic smem: Ws[4096] | bs[64] | vbuf[64*128]
// ---------------------------------------------------------------------------
__global__ __launch_bounds__(512) void v_kernel(const float* __restrict__ x,
                                                const float* __restrict__ Wv,
                                                const float* __restrict__ bv)
{
    extern __shared__ float dsm[];
    float* Ws   = dsm;
    float* bs   = dsm + 4096;
    float* vbuf = dsm + 4160;

    int h = blockIdx.x;
    int tid = threadIdx.x;
    for (int i = tid; i < 4096; i += 512) Ws[i] = Wv[i];
    if (tid < 64) bs[tid] = bv[tid];
    __syncthreads();

    int slot = tid & 127;
    int quarter = tid >> 7;
    int ch0 = quarter * 16;
    int n = h * 128 + slot;

    u64 acc[16];
    #pragma unroll
    for (int i = 0; i < 16; i++) acc[i] = 0ull;

    #pragma unroll 4
    for (int c = 0; c < 64; c += 2) {
        u64 xp = pack2(x[c * NPIX + n], x[(c + 1) * NPIX + n]);
        #pragma unroll
        for (int i = 0; i < 16; i++)
            acc[i] = fma2(xp, *(const u64*)&Ws[(ch0 + i)*64 + c], acc[i]);
    }
    #pragma unroll
    for (int i = 0; i < 16; i++) {
        float2 u = unpack2(acc[i]);
        vbuf[(ch0 + i)*128 + slot] = u.x + u.y + bs[ch0 + i];
    }
    __syncthreads();
    int klo = (slot - 3 < 0) ? 0 : slot - 3;
    int khi = (slot + 3 > 127) ? 127 : slot + 3;
    #pragma unroll
    for (int i = 0; i < 16; i++) {
        const float* vr = vbuf + (ch0 + i)*128;
        float s = 0.f;
        for (int kk = klo; kk <= khi; kk++) s += vr[kk];
        g_tmp[(ch0 + i)*NPIX + h*128 + slot] = s;
    }
}

// ---------------------------------------------------------------------------
// In-place prefix sums: g_S over r (16384 scalar chains), g_tmp over h (8192).
// 96 blocks x 256 threads; MLP = 16 independent LDGs per batch.
// ---------------------------------------------------------------------------
__global__ __launch_bounds__(256) void prefix_kernel()
{
    int t = blockIdx.x * 256 + threadIdx.x;
    float vals[16];
    if (t < 16384) {
        float s = 0.f;
        float* p = g_S + t;
        #pragma unroll
        for (int rb = 0; rb < 128; rb += 16) {
            #pragma unroll
            for (int i = 0; i < 16; i++) vals[i] = p[(rb + i) * 16384];
            #pragma unroll
            for (int i = 0; i < 16; i++) { s += vals[i]; p[(rb + i) * 16384] = s; }
        }
    } else {
        int u = t - 16384;
        int c = u >> 7, k = u & 127;
        float s = 0.f;
        float* p = g_tmp + c * NPIX + k;
        #pragma unroll
        for (int hb = 0; hb < 128; hb += 16) {
            #pragma unroll
            for (int i = 0; i < 16; i++) vals[i] = p[(hb + i) * 128];
            #pragma unroll
            for (int i = 0; i < 16; i++) { s += vals[i]; p[(hb + i) * 128] = s; }
        }
    }
}

// ---------------------------------------------------------------------------
// Per (h, w-half): A = PS diff; softmax_k; Vs = Ptmp diff; out = attn @ Vs^T.
// 256 blocks x 512 threads (round-13 proven config: Vs warp-uniform broadcast,
// A lane-strided conflict-free LDS.128).
// ---------------------------------------------------------------------------
__global__ __launch_bounds__(512) void attn_out_kernel(float* __restrict__ out)
{
    extern __shared__ float sm[];
    float* A  = sm;                 // [64 local w][k], stride ASTR
    float* Vs = sm + 64*ASTR;       // [c=64][k=128]

    int h    = blockIdx.x >> 1;
    int half = blockIdx.x & 1;
    int tid = threadIdx.x;
    int lane = tid & 31, warp = tid >> 5;    // 16 warps

    int r0 = (h - 3 < 0) ? 0 : h - 3;
    int r1 = (h + 3 > 127) ? 127 : h + 3;
    const float4* P1 = (const float4*)(g_S + r1 * 16384 + half * 8192);
    const float4* P0 = (r0 > 0) ? (const float4*)(g_S + (r0 - 1) * 16384 + half * 8192) : nullptr;
    for (int i4 = tid; i4 < 2048; i4 += 512) {
        float4 s = P1[i4];
        if (P0) {
            float4 b = P0[i4];
            s.x -= b.x; s.y -= b.y; s.z -= b.z; s.w -= b.w;
        }
        int wl = i4 >> 5, k = (i4 & 31) * 4;
        *(float4*)(A + wl*ASTR + k) = s;
    }

    int top = (h + 3 > 127) ? 127 : h + 3;
    int bot = h - 4;
    const float4* T4 = (const float4*)g_tmp;
    float4* Vs4 = (float4*)Vs;
    for (int i4 = tid; i4 < 2048; i4 += 512) {
        int c = i4 >> 5, kq = i4 & 31;
        float4 s = T4[c*4096 + top*32 + kq];
        if (bot >= 0) {
            float4 b = T4[c*4096 + bot*32 + kq];
            s.x -= b.x; s.y -= b.y; s.z -= b.z; s.w -= b.w;
        }
        Vs4[c*32 + kq] = s;
    }
    __syncthreads();

    // softmax over k: one warp per local-w row (16 warps cover 64 rows)
    for (int w = warp; w < 64; w += 16) {
        float v[4];
        #pragma unroll
        for (int m = 0; m < 4; m++) v[m] = A[w*ASTR + lane + 32*m];
        float mx = fmaxf(fmaxf(v[0], v[1]), fmaxf(v[2], v[3]));
        #pragma unroll
        for (int off = 16; off > 0; off >>= 1)
            mx = fmaxf(mx, __shfl_xor_sync(0xffffffffu, mx, off));
        float e[4], s = 0.f;
        #pragma unroll
        for (int m = 0; m < 4; m++) { e[m] = __expf(v[m] - mx); s += e[m]; }
        #pragma unroll
        for (int off = 16; off > 0; off >>= 1)
            s += __shfl_xor_sync(0xffffffffu, s, off);
        float inv = 1.f / s;
        #pragma unroll
        for (int m = 0; m < 4; m++) A[w*ASTR + lane + 32*m] = e[m] * inv;
    }
    __syncthreads();

    // out[c, h, half*64 + w] = sum_k A[w][k] * Vs[c][k]  (k packed in pairs)
    int c0 = warp * 4;
    u64 acc[4][2];
    #pragma unroll
    for (int i = 0; i < 4; i++)
        #pragma unroll
        for (int m = 0; m < 2; m++) acc[i][m] = 0ull;

    #pragma unroll 2
    for (int k = 0; k < 128; k += 4) {
        ulonglong2 a0 = *(const ulonglong2*)&A[lane*ASTR + k];
        ulonglong2 a1 = *(const ulonglong2*)&A[(lane + 32)*ASTR + k];
        #pragma unroll
        for (int i = 0; i < 4; i++) {
            ulonglong2 v = *(const ulonglong2*)&Vs[(c0 + i)*128 + k];
            acc[i][0] = fma2(v.x, a0.x, acc[i][0]);
            acc[i][0] = fma2(v.y, a0.y, acc[i][0]);
            acc[i][1] = fma2(v.x, a1.x, acc[i][1]);
            acc[i][1] = fma2(v.y, a1.y, acc[i][1]);
        }
    }
    int wbase = h*128 + half*64 + lane;
    #pragma unroll
    for (int i = 0; i < 4; i++)
        #pragma unroll
        for (int m = 0; m < 2; m++) {
            float2 u = unpack2(acc[i][m]);
            out[(c0 + i)*NPIX + wbase + 32*m] = u.x + u.y;
        }
}

// ---------------------------------------------------------------------------
extern "C" void kernel_launch(void* const* d_in, const int* in_sizes, int n_in,
                              void* d_out, int out_size)
{
    const float* x  = (const float*)d_in[0];
    const float* Wq = (const float*)d_in[1];
    const float* bq = (const float*)d_in[2];
    const float* Wk = (const float*)d_in[3];
    const float* bk = (const float*)d_in[4];
    const float* Wv = (const float*)d_in[5];
    const float* bv = (const float*)d_in[6];
    float* out = (float*)d_out;

    const int smemQ = (8704 + 8704 + 16512) * 4;         // 135680 B
    const int smemV = (4096 + 64 + 64*128) * 4;          //  49664 B
    const int smemA = (64*ASTR + 64*128) * 4;            //  66560 B
    cudaFuncSetAttribute(qkgram_kernel,   cudaFuncAttributeMaxDynamicSharedMemorySize, smemQ);
    cudaFuncSetAttribute(v_kernel,        cudaFuncAttributeMaxDynamicSharedMemorySize, smemV);
    cudaFuncSetAttribute(attn_out_kernel, cudaFuncAttributeMaxDynamicSharedMemorySize, smemA);

    qkgram_kernel<<<128, 512, smemQ>>>(x, Wq, bq, Wk, bk);
    v_kernel<<<128, 512, smemV>>>(x, Wv, bv);
    prefix_kernel<<<96, 256>>>();
    attn_out_kernel<<<256, 512, smemA>>>(out);
}